// round 2
// baseline (speedup 1.0000x reference)
#include <cuda_runtime.h>

#define NB 4
#define NN 16384
#define NEG 131072
#define NH 4
#define NDK 32
#define NDM 128

// ---------------- device scratch (no allocs allowed) ----------------
__device__ float g_Q[NB * NN * NDM];
__device__ float g_K[NB * NN * NDM];
__device__ float g_V[NB * NN * NDM];
__device__ float g_num[NB * NN * NDM];
__device__ float g_den[NB * NN * NH];

// ---------------- packed f32x2 helpers (Blackwell) ----------------
__device__ __forceinline__ unsigned long long pack2(float a, float b) {
    unsigned long long r;
    asm("mov.b64 %0, {%1,%2};" : "=l"(r) : "f"(a), "f"(b));
    return r;
}
__device__ __forceinline__ void unpack2(unsigned long long v, float& a, float& b) {
    asm("mov.b64 {%0,%1}, %2;" : "=f"(a), "=f"(b) : "l"(v));
}
__device__ __forceinline__ unsigned long long fma2(unsigned long long a, unsigned long long b,
                                                   unsigned long long c) {
    unsigned long long r;
    asm("fma.rn.f32x2 %0, %1, %2, %3;" : "=l"(r) : "l"(a), "l"(b), "l"(c));
    return r;
}

__device__ __forceinline__ float wsum(float v) {
#pragma unroll
    for (int o = 16; o; o >>= 1) v += __shfl_xor_sync(0xffffffffu, v, o);
    return v;
}

// Warp computes row(128) @ Wsmem(128x128). Lane l returns output cols [4l..4l+3].
// Wsmem stored row-major [k][128]; lane-l LDS128 at k*128+4l is conflict-free.
__device__ __forceinline__ float4 warp_row_gemm(const float* __restrict__ x,
                                                const float* __restrict__ Ws, int lane) {
    unsigned long long a01 = 0ull, a23 = 0ull;  // bit pattern (0.f,0.f)
#pragma unroll 8
    for (int g = 0; g < 32; ++g) {
        float4 x4 = *reinterpret_cast<const float4*>(x + 4 * g);  // broadcast
        const float* wp = Ws + (4 * g) * NDM + 4 * lane;
        float xs[4] = {x4.x, x4.y, x4.z, x4.w};
#pragma unroll
        for (int kk = 0; kk < 4; ++kk) {
            float4 w = *reinterpret_cast<const float4*>(wp + kk * NDM);
            unsigned long long xx = pack2(xs[kk], xs[kk]);
            a01 = fma2(xx, pack2(w.x, w.y), a01);
            a23 = fma2(xx, pack2(w.z, w.w), a23);
        }
    }
    float4 r;
    unpack2(a01, r.x, r.y);
    unpack2(a23, r.z, r.w);
    return r;
}

// Load W (128x128, cols j = h*32+d) into smem permuted to cols j' = d*4+h.
__device__ __forceinline__ void load_W_headperm(const float* __restrict__ W, float* Wr) {
    for (int idx = threadIdx.x; idx < NDM * NDM; idx += blockDim.x) {
        int c = idx & (NDM - 1);
        int d = c >> 2, h = c & 3;
        Wr[idx] = W[(idx - c) + h * NDK + d];
    }
}

// ---------------- kernel 1: projections Y[r, d*4+h] = X[r,:] @ W[:, h*32+d] ----------------
__global__ void proj_kernel(const float* __restrict__ X, const float* __restrict__ W,
                            float* __restrict__ Y, int nrows) {
    extern __shared__ float sm[];
    float* Wr = sm;
    float* stage = sm + NDM * NDM;
    load_W_headperm(W, Wr);
    __syncthreads();

    const int lane = threadIdx.x & 31;
    const int warp = threadIdx.x >> 5;
    float* xrow = stage + warp * NDM;
    int gw = blockIdx.x * (blockDim.x >> 5) + warp;
    int nw = gridDim.x * (blockDim.x >> 5);

    for (int r = gw; r < nrows; r += nw) {
        float4 x4 = *reinterpret_cast<const float4*>(X + (long long)r * NDM + 4 * lane);
        *reinterpret_cast<float4*>(xrow + 4 * lane) = x4;
        __syncwarp();
        float4 y = warp_row_gemm(xrow, Wr, lane);
        *reinterpret_cast<float4*>(Y + (long long)r * NDM + 4 * lane) = y;
        __syncwarp();
    }
}

// ---------------- kernel 2: fused E-proj + edge attention + scatter ----------------
__global__ void edge_kernel(const int* __restrict__ eidx, const float* __restrict__ ef,
                            const float* __restrict__ WE, float* __restrict__ attn_out) {
    extern __shared__ float sm[];
    float* Wr = sm;
    float* stage = sm + NDM * NDM;
    load_W_headperm(WE, Wr);
    __syncthreads();

    const int lane = threadIdx.x & 31;
    const int warp = threadIdx.x >> 5;
    float* xrow = stage + warp * NDM;
    int gw = blockIdx.x * (blockDim.x >> 5) + warp;
    int nw = gridDim.x * (blockDim.x >> 5);
    const float scale = 0.1767766952966369f;  // 1/sqrt(32)

    const int total = NB * NEG;
    for (int t = gw; t < total; t += nw) {
        int b = t >> 17;            // / NEG
        int e = t & (NEG - 1);      // % NEG
        int src = eidx[(b * 2) * NEG + e];
        int tgt = eidx[(b * 2 + 1) * NEG + e];

        // stage edge-feature row
        float4 e4 = *reinterpret_cast<const float4*>(ef + (long long)t * NDM + 4 * lane);
        *reinterpret_cast<float4*>(xrow + 4 * lane) = e4;
        __syncwarp();

        // E[h, d=lane] for h=0..3 in E.x..E.w
        float4 E = warp_row_gemm(xrow, Wr, lane);

        int qrow = b * NN + src;
        int krow = b * NN + tgt;
        float4 q = *reinterpret_cast<const float4*>(g_Q + (long long)qrow * NDM + 4 * lane);
        float4 k = *reinterpret_cast<const float4*>(g_K + (long long)krow * NDM + 4 * lane);
        float4 v = *reinterpret_cast<const float4*>(g_V + (long long)krow * NDM + 4 * lane);

        float p0 = wsum(q.x * k.x * E.x);
        float p1 = wsum(q.y * k.y * E.y);
        float p2 = wsum(q.z * k.z * E.z);
        float p3 = wsum(q.w * k.w * E.w);

        float a0 = expf(fminf(fmaxf(p0 * scale, -5.f), 5.f));
        float a1 = expf(fminf(fmaxf(p1 * scale, -5.f), 5.f));
        float a2 = expf(fminf(fmaxf(p2 * scale, -5.f), 5.f));
        float a3 = expf(fminf(fmaxf(p3 * scale, -5.f), 5.f));

        float* np = g_num + (long long)qrow * NDM + 4 * lane;
        atomicAdd(np + 0, a0 * v.x);
        atomicAdd(np + 1, a1 * v.y);
        atomicAdd(np + 2, a2 * v.z);
        atomicAdd(np + 3, a3 * v.w);
        if (lane < 4) {
            float aa = lane == 0 ? a0 : (lane == 1 ? a1 : (lane == 2 ? a2 : a3));
            atomicAdd(g_den + qrow * NH + lane, aa);
            if (b == NB - 1) attn_out[(long long)lane * NEG + e] = aa;
        }
        __syncwarp();
    }
}

// ---------------- kernel 3: num/den -> @W_fc -> +residual -> layernorm ----------------
__global__ void finalize_kernel(const float* __restrict__ residual, const float* __restrict__ Wfc,
                                const float* __restrict__ gamma, const float* __restrict__ beta,
                                float* __restrict__ out) {
    extern __shared__ float sm[];
    float* Wr = sm;
    float* stage = sm + NDM * NDM;
    // permute W_fc ROWS: smem row j' = d*4+h holds W_fc[h*32+d, :]
    for (int idx = threadIdx.x; idx < NDM * NDM; idx += blockDim.x) {
        int jp = idx >> 7, m = idx & 127;
        int srow = (jp & 3) * NDK + (jp >> 2);
        Wr[idx] = Wfc[srow * NDM + m];
    }
    __syncthreads();

    const int lane = threadIdx.x & 31;
    const int warp = threadIdx.x >> 5;
    float* xrow = stage + warp * NDM;
    int gw = blockIdx.x * (blockDim.x >> 5) + warp;
    int nw = gridDim.x * (blockDim.x >> 5);

    float4 g4 = *reinterpret_cast<const float4*>(gamma + 4 * lane);
    float4 b4 = *reinterpret_cast<const float4*>(beta + 4 * lane);

    for (int r = gw; r < NB * NN; r += nw) {
        float4 num4 = *reinterpret_cast<const float4*>(g_num + (long long)r * NDM + 4 * lane);
        float4 den4 = *reinterpret_cast<const float4*>(g_den + r * NH);  // broadcast
        float4 o;
        o.x = num4.x / (den4.x + 1e-8f);
        o.y = num4.y / (den4.y + 1e-8f);
        o.z = num4.z / (den4.z + 1e-8f);
        o.w = num4.w / (den4.w + 1e-8f);
        *reinterpret_cast<float4*>(xrow + 4 * lane) = o;
        __syncwarp();

        float4 y = warp_row_gemm(xrow, Wr, lane);
        float4 res = *reinterpret_cast<const float4*>(residual + (long long)r * NDM + 4 * lane);
        y.x += res.x; y.y += res.y; y.z += res.z; y.w += res.w;

        float s = wsum(y.x + y.y + y.z + y.w);
        float ss = wsum(y.x * y.x + y.y * y.y + y.z * y.z + y.w * y.w);
        float mu = s * (1.f / 128.f);
        float var = ss * (1.f / 128.f) - mu * mu;
        float rs = rsqrtf(var + 1e-5f);

        float4 o2;
        o2.x = g4.x * (y.x - mu) * rs + b4.x;
        o2.y = g4.y * (y.y - mu) * rs + b4.y;
        o2.z = g4.z * (y.z - mu) * rs + b4.z;
        o2.w = g4.w * (y.w - mu) * rs + b4.w;
        *reinterpret_cast<float4*>(out + (long long)r * NDM + 4 * lane) = o2;
        __syncwarp();
    }
}

// ---------------- launch ----------------
extern "C" void kernel_launch(void* const* d_in, const int* in_sizes, int n_in,
                              void* d_out, int out_size) {
    const int*   eidx = (const int*)d_in[0];
    const float* ef   = (const float*)d_in[1];
    const float* iQ   = (const float*)d_in[2];
    const float* iK   = (const float*)d_in[3];
    const float* iV   = (const float*)d_in[4];
    const float* WQ   = (const float*)d_in[5];
    const float* WK   = (const float*)d_in[6];
    const float* WV   = (const float*)d_in[7];
    const float* WE   = (const float*)d_in[8];
    const float* Wfc  = (const float*)d_in[9];
    const float* gam  = (const float*)d_in[10];
    const float* bet  = (const float*)d_in[11];

    float* out = (float*)d_out;
    float* attn_out = out + (long long)NB * NN * NDM;

    const size_t SMEM = (size_t)(NDM * NDM + 8 * NDM) * sizeof(float);  // 69632 B
    cudaFuncSetAttribute(proj_kernel, cudaFuncAttributeMaxDynamicSharedMemorySize, (int)SMEM);
    cudaFuncSetAttribute(edge_kernel, cudaFuncAttributeMaxDynamicSharedMemorySize, (int)SMEM);
    cudaFuncSetAttribute(finalize_kernel, cudaFuncAttributeMaxDynamicSharedMemorySize, (int)SMEM);

    void *np, *dp, *qp, *kp, *vp;
    cudaGetSymbolAddress(&np, g_num);
    cudaGetSymbolAddress(&dp, g_den);
    cudaGetSymbolAddress(&qp, g_Q);
    cudaGetSymbolAddress(&kp, g_K);
    cudaGetSymbolAddress(&vp, g_V);

    cudaMemsetAsync(np, 0, sizeof(g_num));
    cudaMemsetAsync(dp, 0, sizeof(g_den));

    dim3 blk(256);
    proj_kernel<<<444, blk, SMEM>>>(iQ, WQ, (float*)qp, NB * NN);
    proj_kernel<<<444, blk, SMEM>>>(iK, WK, (float*)kp, NB * NN);
    proj_kernel<<<444, blk, SMEM>>>(iV, WV, (float*)vp, NB * NN);
    edge_kernel<<<444, blk, SMEM>>>(eidx, ef, WE, attn_out);
    finalize_kernel<<<444, blk, SMEM>>>(iQ, Wfc, gam, bet, out);
}

// round 4
// speedup vs baseline: 3.9907x; 3.9907x over previous
#include <cuda_runtime.h>

#define NB 4
#define NN 16384
#define NEG 131072
#define NH 4
#define NDK 32
#define NDM 128
#define EPB 8  // rows (edges) per warp block

// ---------------- device scratch (no allocs allowed) ----------------
__device__ float g_Q[NB * NN * NDM];
__device__ float g_K[NB * NN * NDM];
__device__ float g_V[NB * NN * NDM];
__device__ float g_num[NB * NN * NDM];
__device__ float g_den[NB * NN * NH];

// ---------------- packed f32x2 helpers (Blackwell) ----------------
__device__ __forceinline__ unsigned long long pack2(float a, float b) {
    unsigned long long r;
    asm("mov.b64 %0, {%1,%2};" : "=l"(r) : "f"(a), "f"(b));
    return r;
}
__device__ __forceinline__ void unpack2(unsigned long long v, float& a, float& b) {
    asm("mov.b64 {%0,%1}, %2;" : "=f"(a), "=f"(b) : "l"(v));
}
__device__ __forceinline__ unsigned long long fma2(unsigned long long a, unsigned long long b,
                                                   unsigned long long c) {
    unsigned long long r;
    asm("fma.rn.f32x2 %0, %1, %2, %3;" : "=l"(r) : "l"(a), "l"(b), "l"(c));
    return r;
}

__device__ __forceinline__ float wsum(float v) {
#pragma unroll
    for (int o = 16; o; o >>= 1) v += __shfl_xor_sync(0xffffffffu, v, o);
    return v;
}

// Warp computes 8 rows (each 128) @ Wsmem(128x128) simultaneously.
// xs: 8 staged rows (stride NDM). Lane l gets output cols [4l..4l+3] of each row.
// W read once per 8 rows -> smem traffic /8 vs matvec.
__device__ __forceinline__ void warp_block_gemm8(const float* __restrict__ xs,
                                                 const float* __restrict__ Ws, int lane,
                                                 float4* __restrict__ out) {
    unsigned long long a01[EPB], a23[EPB];
#pragma unroll
    for (int e = 0; e < EPB; ++e) { a01[e] = 0ull; a23[e] = 0ull; }

#pragma unroll 2
    for (int g = 0; g < 32; ++g) {
        const float* wp = Ws + (4 * g) * NDM + 4 * lane;
        float4 w0 = *reinterpret_cast<const float4*>(wp);
        float4 w1 = *reinterpret_cast<const float4*>(wp + NDM);
        float4 w2 = *reinterpret_cast<const float4*>(wp + 2 * NDM);
        float4 w3 = *reinterpret_cast<const float4*>(wp + 3 * NDM);
        unsigned long long w0a = pack2(w0.x, w0.y), w0b = pack2(w0.z, w0.w);
        unsigned long long w1a = pack2(w1.x, w1.y), w1b = pack2(w1.z, w1.w);
        unsigned long long w2a = pack2(w2.x, w2.y), w2b = pack2(w2.z, w2.w);
        unsigned long long w3a = pack2(w3.x, w3.y), w3b = pack2(w3.z, w3.w);
#pragma unroll
        for (int e = 0; e < EPB; ++e) {
            float4 x = *reinterpret_cast<const float4*>(xs + e * NDM + 4 * g);  // broadcast
            unsigned long long xx;
            xx = pack2(x.x, x.x); a01[e] = fma2(xx, w0a, a01[e]); a23[e] = fma2(xx, w0b, a23[e]);
            xx = pack2(x.y, x.y); a01[e] = fma2(xx, w1a, a01[e]); a23[e] = fma2(xx, w1b, a23[e]);
            xx = pack2(x.z, x.z); a01[e] = fma2(xx, w2a, a01[e]); a23[e] = fma2(xx, w2b, a23[e]);
            xx = pack2(x.w, x.w); a01[e] = fma2(xx, w3a, a01[e]); a23[e] = fma2(xx, w3b, a23[e]);
        }
    }
#pragma unroll
    for (int e = 0; e < EPB; ++e) {
        unpack2(a01[e], out[e].x, out[e].y);
        unpack2(a23[e], out[e].z, out[e].w);
    }
}

// Load W (128x128, cols j = h*32+d) into smem permuted to cols j' = d*4+h.
__device__ __forceinline__ void load_W_headperm(const float* __restrict__ W, float* Wr) {
    for (int idx = threadIdx.x; idx < NDM * NDM; idx += blockDim.x) {
        int c = idx & (NDM - 1);
        int d = c >> 2, h = c & 3;
        Wr[idx] = W[(idx - c) + h * NDK + d];
    }
}

#define SMEM_FLOATS (NDM * NDM + 8 * EPB * NDM)

// ---------------- kernel 1: projections, 8 rows per warp ----------------
__global__ __launch_bounds__(256, 2) void proj_kernel(const float* __restrict__ X,
                                                      const float* __restrict__ W,
                                                      float* __restrict__ Y, int nrows) {
    extern __shared__ float sm[];
    float* Wr = sm;
    load_W_headperm(W, Wr);
    __syncthreads();

    const int lane = threadIdx.x & 31;
    const int warp = threadIdx.x >> 5;
    float* xs = sm + NDM * NDM + warp * EPB * NDM;
    int gw = blockIdx.x * (blockDim.x >> 5) + warp;
    int nw = gridDim.x * (blockDim.x >> 5);
    const int ngroups = nrows / EPB;

    for (int gi = gw; gi < ngroups; gi += nw) {
        long long r0 = (long long)gi * EPB;
#pragma unroll
        for (int e = 0; e < EPB; ++e) {
            float4 x4 = *reinterpret_cast<const float4*>(X + (r0 + e) * NDM + 4 * lane);
            *reinterpret_cast<float4*>(xs + e * NDM + 4 * lane) = x4;
        }
        __syncwarp();
        float4 y[EPB];
        warp_block_gemm8(xs, Wr, lane, y);
#pragma unroll
        for (int e = 0; e < EPB; ++e)
            *reinterpret_cast<float4*>(Y + (r0 + e) * NDM + 4 * lane) = y[e];
        __syncwarp();
    }
}

// ---------------- kernel 2: fused E-proj + edge attention + scatter, 8 edges/warp ----------------
__global__ __launch_bounds__(256, 2) void edge_kernel(const int* __restrict__ eidx,
                                                      const float* __restrict__ ef,
                                                      const float* __restrict__ WE,
                                                      float* __restrict__ attn_out) {
    extern __shared__ float sm[];
    float* Wr = sm;
    load_W_headperm(WE, Wr);
    __syncthreads();

    const int lane = threadIdx.x & 31;
    const int warp = threadIdx.x >> 5;
    float* xs = sm + NDM * NDM + warp * EPB * NDM;
    int gw = blockIdx.x * (blockDim.x >> 5) + warp;
    int nw = gridDim.x * (blockDim.x >> 5);
    const float scale = 0.1767766952966369f;  // 1/sqrt(32)

    const int ngroups = NB * NEG / EPB;      // 65536
    const int gpb = NEG / EPB;               // 16384 groups per batch

    for (int gi = gw; gi < ngroups; gi += nw) {
        int b = gi / gpb;
        int e0 = (gi - b * gpb) * EPB;

        // lane-parallel index loads (lanes 0..7)
        int src_l = 0, tgt_l = 0;
        if (lane < EPB) {
            src_l = eidx[(b * 2) * NEG + e0 + lane];
            tgt_l = eidx[(b * 2 + 1) * NEG + e0 + lane];
        }

        // stage 8 edge-feature rows
        long long t0 = (long long)b * NEG + e0;
#pragma unroll
        for (int e = 0; e < EPB; ++e) {
            float4 x4 = *reinterpret_cast<const float4*>(ef + (t0 + e) * NDM + 4 * lane);
            *reinterpret_cast<float4*>(xs + e * NDM + 4 * lane) = x4;
        }
        __syncwarp();

        // E[e][h] for h=0..3 at d=lane
        float4 Ev[EPB];
        warp_block_gemm8(xs, Wr, lane, Ev);

        // epilogue in 2 chunks of 4 edges (bounded reg pressure, batched loads for MLP)
#pragma unroll
        for (int c = 0; c < 2; ++c) {
            float4 q[4], k4[4], v4[4];
            int qr[4];
#pragma unroll
            for (int i = 0; i < 4; ++i) {
                int e = c * 4 + i;
                int src = __shfl_sync(0xffffffffu, src_l, e);
                int tgt = __shfl_sync(0xffffffffu, tgt_l, e);
                qr[i] = b * NN + src;
                int kr = b * NN + tgt;
                q[i]  = *reinterpret_cast<const float4*>(g_Q + (long long)qr[i] * NDM + 4 * lane);
                k4[i] = *reinterpret_cast<const float4*>(g_K + (long long)kr * NDM + 4 * lane);
                v4[i] = *reinterpret_cast<const float4*>(g_V + (long long)kr * NDM + 4 * lane);
            }
#pragma unroll
            for (int i = 0; i < 4; ++i) {
                int e = c * 4 + i;
                float4 E = Ev[e];
                float p0 = wsum(q[i].x * k4[i].x * E.x);
                float p1 = wsum(q[i].y * k4[i].y * E.y);
                float p2 = wsum(q[i].z * k4[i].z * E.z);
                float p3 = wsum(q[i].w * k4[i].w * E.w);

                float a0 = expf(fminf(fmaxf(p0 * scale, -5.f), 5.f));
                float a1 = expf(fminf(fmaxf(p1 * scale, -5.f), 5.f));
                float a2 = expf(fminf(fmaxf(p2 * scale, -5.f), 5.f));
                float a3 = expf(fminf(fmaxf(p3 * scale, -5.f), 5.f));

                float* np = g_num + (long long)qr[i] * NDM + 4 * lane;
                atomicAdd(np + 0, a0 * v4[i].x);
                atomicAdd(np + 1, a1 * v4[i].y);
                atomicAdd(np + 2, a2 * v4[i].z);
                atomicAdd(np + 3, a3 * v4[i].w);
                if (lane < 4) {
                    float aa = lane == 0 ? a0 : (lane == 1 ? a1 : (lane == 2 ? a2 : a3));
                    atomicAdd(g_den + qr[i] * NH + lane, aa);
                    if (b == NB - 1) attn_out[(long long)lane * NEG + e0 + e] = aa;
                }
            }
        }
        __syncwarp();
    }
}

// ---------------- kernel 3: num/den -> @W_fc -> +residual -> layernorm, 8 rows/warp ----------------
__global__ __launch_bounds__(256, 2) void finalize_kernel(const float* __restrict__ residual,
                                                          const float* __restrict__ Wfc,
                                                          const float* __restrict__ gamma,
                                                          const float* __restrict__ beta,
                                                          float* __restrict__ out) {
    extern __shared__ float sm[];
    float* Wr = sm;
    // permute W_fc ROWS: smem row j' = d*4+h holds W_fc[h*32+d, :]
    for (int idx = threadIdx.x; idx < NDM * NDM; idx += blockDim.x) {
        int jp = idx >> 7, m = idx & 127;
        int srow = (jp & 3) * NDK + (jp >> 2);
        Wr[idx] = Wfc[srow * NDM + m];
    }
    __syncthreads();

    const int lane = threadIdx.x & 31;
    const int warp = threadIdx.x >> 5;
    float* xs = sm + NDM * NDM + warp * EPB * NDM;
    int gw = blockIdx.x * (blockDim.x >> 5) + warp;
    int nw = gridDim.x * (blockDim.x >> 5);

    float4 g4 = *reinterpret_cast<const float4*>(gamma + 4 * lane);
    float4 b4 = *reinterpret_cast<const float4*>(beta + 4 * lane);
    const int ngroups = NB * NN / EPB;

    for (int gi = gw; gi < ngroups; gi += nw) {
        long long r0 = (long long)gi * EPB;
#pragma unroll
        for (int e = 0; e < EPB; ++e) {
            float4 num4 = *reinterpret_cast<const float4*>(g_num + (r0 + e) * NDM + 4 * lane);
            float4 den4 = *reinterpret_cast<const float4*>(g_den + (r0 + e) * NH);  // broadcast
            float4 o;
            o.x = num4.x / (den4.x + 1e-8f);
            o.y = num4.y / (den4.y + 1e-8f);
            o.z = num4.z / (den4.z + 1e-8f);
            o.w = num4.w / (den4.w + 1e-8f);
            *reinterpret_cast<float4*>(xs + e * NDM + 4 * lane) = o;
        }
        __syncwarp();

        float4 y[EPB];
        warp_block_gemm8(xs, Wr, lane, y);

#pragma unroll
        for (int e = 0; e < EPB; ++e) {
            float4 res = *reinterpret_cast<const float4*>(residual + (r0 + e) * NDM + 4 * lane);
            float4 v = y[e];
            v.x += res.x; v.y += res.y; v.z += res.z; v.w += res.w;

            float s  = wsum(v.x + v.y + v.z + v.w);
            float ss = wsum(v.x * v.x + v.y * v.y + v.z * v.z + v.w * v.w);
            float mu = s * (1.f / 128.f);
            float var = ss * (1.f / 128.f) - mu * mu;
            float rs = rsqrtf(var + 1e-5f);

            float4 o2;
            o2.x = g4.x * (v.x - mu) * rs + b4.x;
            o2.y = g4.y * (v.y - mu) * rs + b4.y;
            o2.z = g4.z * (v.z - mu) * rs + b4.z;
            o2.w = g4.w * (v.w - mu) * rs + b4.w;
            *reinterpret_cast<float4*>(out + (r0 + e) * NDM + 4 * lane) = o2;
        }
        __syncwarp();
    }
}

// ---------------- launch ----------------
extern "C" void kernel_launch(void* const* d_in, const int* in_sizes, int n_in,
                              void* d_out, int out_size) {
    const int*   eidx = (const int*)d_in[0];
    const float* ef   = (const float*)d_in[1];
    const float* iQ   = (const float*)d_in[2];
    const float* iK   = (const float*)d_in[3];
    const float* iV   = (const float*)d_in[4];
    const float* WQ   = (const float*)d_in[5];
    const float* WK   = (const float*)d_in[6];
    const float* WV   = (const float*)d_in[7];
    const float* WE   = (const float*)d_in[8];
    const float* Wfc  = (const float*)d_in[9];
    const float* gam  = (const float*)d_in[10];
    const float* bet  = (const float*)d_in[11];

    float* out = (float*)d_out;
    float* attn_out = out + (long long)NB * NN * NDM;

    const size_t SMEM = (size_t)SMEM_FLOATS * sizeof(float);  // 64KB W + 32KB stage = 96KB
    static int smem_set = 0;
    if (!smem_set) {
        cudaFuncSetAttribute(proj_kernel, cudaFuncAttributeMaxDynamicSharedMemorySize, (int)SMEM);
        cudaFuncSetAttribute(edge_kernel, cudaFuncAttributeMaxDynamicSharedMemorySize, (int)SMEM);
        cudaFuncSetAttribute(finalize_kernel, cudaFuncAttributeMaxDynamicSharedMemorySize, (int)SMEM);
        smem_set = 1;
    }

    void *np, *dp, *qp, *kp, *vp;
    cudaGetSymbolAddress(&np, g_num);
    cudaGetSymbolAddress(&dp, g_den);
    cudaGetSymbolAddress(&qp, g_Q);
    cudaGetSymbolAddress(&kp, g_K);
    cudaGetSymbolAddress(&vp, g_V);

    cudaMemsetAsync(np, 0, sizeof(g_num));
    cudaMemsetAsync(dp, 0, sizeof(g_den));

    dim3 blk(256);
    const int GRID = 296;  // 2 blocks/SM (smem-limited) x 148 SMs
    proj_kernel<<<GRID, blk, SMEM>>>(iQ, WQ, (float*)qp, NB * NN);
    proj_kernel<<<GRID, blk, SMEM>>>(iK, WK, (float*)kp, NB * NN);
    proj_kernel<<<GRID, blk, SMEM>>>(iV, WV, (float*)vp, NB * NN);
    edge_kernel<<<GRID, blk, SMEM>>>(eidx, ef, WE, attn_out);
    finalize_kernel<<<GRID, blk, SMEM>>>(iQ, Wfc, gam, bet, out);
}